// round 12
// baseline (speedup 1.0000x reference)
#include <cuda_runtime.h>
#include <cuda_fp16.h>

#define MAX_N 100000
#define HID   16

// Scratch (allocation-free rule: __device__ globals)
__device__ __align__(16) float   g_deg[MAX_N];
__device__ __align__(16) float   g_dinv[MAX_N];
__device__ __align__(16) __half  g_px[MAX_N];   // fp16: dinv[v]*x[v]  (200KB)
__device__ __align__(16) float   g_s[MAX_N];    // layer-1 aggregate accumulator
__device__ __align__(16) __half2 g_gd[MAX_N];   // fp16x2: dinv[v]*g[v,0:2]
__device__ __align__(16) float2  g_acc[MAX_N];  // layer-2 aggregate accumulator

// no-return global reductions (REDG)
__device__ __forceinline__ void red_add_f32(float* addr, float v) {
    asm volatile("red.global.relaxed.gpu.add.f32 [%0], %1;"
                 :: "l"(addr), "f"(v) : "memory");
}
__device__ __forceinline__ void red_add_v2(float2* addr, float a, float b) {
    asm volatile("red.global.relaxed.gpu.add.v2.f32 [%0], {%1, %2};"
                 :: "l"(addr), "f"(a), "f"(b) : "memory");
}

__device__ __forceinline__ int4 ldcs_int4(const int* p) {
    return __ldcs(reinterpret_cast<const int4*>(p));
}

__device__ __forceinline__ void gdep_sync() {
#if __CUDA_ARCH__ >= 900
    cudaGridDependencySynchronize();
#endif
}
__device__ __forceinline__ void pdl_trigger() {
#if __CUDA_ARCH__ >= 900
    cudaTriggerProgrammaticLaunchCompletion();
#endif
}

// degree histogram over dst, 4 edges/thread (T=512 blocks)
__global__ void k_deg(const int* __restrict__ dst, int E) {
    int i = blockIdx.x * blockDim.x + threadIdx.x;
    int base = i * 4;
    if (base + 3 < E) {
        int4 d = ldcs_int4(dst + base);
        gdep_sync();                       // wait for g_deg memset
        red_add_f32(&g_deg[d.x], 1.0f);
        red_add_f32(&g_deg[d.y], 1.0f);
        red_add_f32(&g_deg[d.z], 1.0f);
        red_add_f32(&g_deg[d.w], 1.0f);
        pdl_trigger();
    } else {
        gdep_sync();
        for (int j = base; j < E; ++j)
            red_add_f32(&g_deg[dst[j]], 1.0f);
        pdl_trigger();
    }
}

// 2 nodes/thread, vectorized (N even)
__global__ void k_dinv_px(const float* __restrict__ x, int n) {
    int i = blockIdx.x * blockDim.x + threadIdx.x;
    int v = i * 2;
    if (v + 1 < n) {
        float2 xv = *reinterpret_cast<const float2*>(x + v);
        gdep_sync();                       // wait for k_deg
        float2 dg = *reinterpret_cast<const float2*>(g_deg + v);
        float d0 = rsqrtf(dg.x + 1.0f);    // +1 = self-loop
        float d1 = rsqrtf(dg.y + 1.0f);
        *reinterpret_cast<float2*>(g_dinv + v) = make_float2(d0, d1);
        *reinterpret_cast<__half2*>(g_px + v)  = __floats2half2_rn(d0 * xv.x, d1 * xv.y);
        *reinterpret_cast<float2*>(g_s + v)    = make_float2(0.0f, 0.0f);
        pdl_trigger();
    } else {
        gdep_sync();
        for (int j = v; j < n; ++j) {
            float dv = rsqrtf(g_deg[j] + 1.0f);
            g_dinv[j] = dv;
            g_px[j]   = __float2half_rn(dv * x[j]);
            g_s[j]    = 0.0f;
        }
        pdl_trigger();
    }
}

// scatter 1: s[dst] += px[src], 4 edges/thread (T=512 blocks)
__global__ void k_scatter1(const int* __restrict__ src,
                           const int* __restrict__ dst, int E) {
    int i = blockIdx.x * blockDim.x + threadIdx.x;
    int base = i * 4;
    if (base + 3 < E) {
        int4 s4 = ldcs_int4(src + base);
        int4 d4 = ldcs_int4(dst + base);
        gdep_sync();                       // wait for k_dinv_px (px, s=0)
        float p0 = __half2float(__ldg(&g_px[s4.x]));
        float p1 = __half2float(__ldg(&g_px[s4.y]));
        float p2 = __half2float(__ldg(&g_px[s4.z]));
        float p3 = __half2float(__ldg(&g_px[s4.w]));
        red_add_f32(&g_s[d4.x], p0);
        red_add_f32(&g_s[d4.y], p1);
        red_add_f32(&g_s[d4.z], p2);
        red_add_f32(&g_s[d4.w], p3);
        pdl_trigger();
    } else {
        gdep_sync();
        for (int j = base; j < E; ++j)
            red_add_f32(&g_s[dst[j]], __half2float(__ldg(&g_px[src[j]])));
        pdl_trigger();
    }
}

// per-node dense, 2 nodes/thread: finalize s, W1/b1 + relu, W2, pre-scale by dinv
// prologue: weights staged to SMEM (inputs — safe pre-dependency)
__global__ void k_node(const float* __restrict__ W1, const float* __restrict__ b1,
                       const float* __restrict__ W2, int n) {
    __shared__ float sw1[HID], sb1[HID], sw2[2 * HID];
    int t = threadIdx.x;
    if (t < HID)     { sw1[t] = __ldg(&W1[t]); sb1[t] = __ldg(&b1[t]); }
    if (t < 2 * HID) { sw2[t] = __ldg(&W2[t]); }
    __syncthreads();
    gdep_sync();                           // wait for k_scatter1
    int v = (blockIdx.x * blockDim.x + t) * 2;
    if (v + 1 < n) {
        float2 dv2 = *reinterpret_cast<const float2*>(g_dinv + v);
        float2 s2  = *reinterpret_cast<const float2*>(g_s + v);
        float2 px2 = __half22float2(*reinterpret_cast<const __half2*>(g_px + v));
        float sa = dv2.x * (s2.x + px2.x);   // + self-loop terms
        float sb = dv2.y * (s2.y + px2.y);
        float a0 = 0.0f, a1 = 0.0f, c0 = 0.0f, c1 = 0.0f;
#pragma unroll
        for (int j = 0; j < HID; ++j) {
            float ha = fmaxf(fmaf(sa, sw1[j], sb1[j]), 0.0f);
            float hb = fmaxf(fmaf(sb, sw1[j], sb1[j]), 0.0f);
            a0 = fmaf(ha, sw2[2 * j + 0], a0);
            a1 = fmaf(ha, sw2[2 * j + 1], a1);
            c0 = fmaf(hb, sw2[2 * j + 0], c0);
            c1 = fmaf(hb, sw2[2 * j + 1], c1);
        }
        __half2 ga = __floats2half2_rn(dv2.x * a0, dv2.x * a1);
        __half2 gb = __floats2half2_rn(dv2.y * c0, dv2.y * c1);
        __half2* gp = g_gd + v;
        gp[0] = ga;
        gp[1] = gb;
        *reinterpret_cast<float4*>(g_acc + v) = make_float4(0.f, 0.f, 0.f, 0.f);
    } else if (v < n) {                    // odd-N tail (not hit for N=100000)
        float dv = g_dinv[v];
        float sv = dv * (g_s[v] + __half2float(g_px[v]));
        float a0 = 0.0f, a1 = 0.0f;
#pragma unroll
        for (int j = 0; j < HID; ++j) {
            float h = fmaxf(fmaf(sv, sw1[j], sb1[j]), 0.0f);
            a0 = fmaf(h, sw2[2 * j + 0], a0);
            a1 = fmaf(h, sw2[2 * j + 1], a1);
        }
        g_gd[v]  = __floats2half2_rn(dv * a0, dv * a1);
        g_acc[v] = make_float2(0.0f, 0.0f);
    }
    pdl_trigger();
}

// scatter 2: acc[dst] += gd[src] via ONE red.v2 per edge, 4 edges/thread (T=512)
__global__ void k_scatter2(const int* __restrict__ src,
                           const int* __restrict__ dst, int E) {
    int i = blockIdx.x * blockDim.x + threadIdx.x;
    int base = i * 4;
    if (base + 3 < E) {
        int4 s4 = ldcs_int4(src + base);
        int4 d4 = ldcs_int4(dst + base);
        gdep_sync();                       // wait for k_node (gd, acc=0)
        float2 a0 = __half22float2(__ldg(&g_gd[s4.x]));
        float2 a1 = __half22float2(__ldg(&g_gd[s4.y]));
        float2 a2 = __half22float2(__ldg(&g_gd[s4.z]));
        float2 a3 = __half22float2(__ldg(&g_gd[s4.w]));
        red_add_v2(&g_acc[d4.x], a0.x, a0.y);
        red_add_v2(&g_acc[d4.y], a1.x, a1.y);
        red_add_v2(&g_acc[d4.z], a2.x, a2.y);
        red_add_v2(&g_acc[d4.w], a3.x, a3.y);
        pdl_trigger();
    } else {
        gdep_sync();
        for (int j = base; j < E; ++j) {
            float2 a = __half22float2(__ldg(&g_gd[src[j]]));
            red_add_v2(&g_acc[dst[j]], a.x, a.y);
        }
        pdl_trigger();
    }
}

// 2 nodes/thread; prologue: bias loads (inputs); float4 store
__global__ void k_final(const float* __restrict__ b2, float2* __restrict__ out, int n) {
    int i = blockIdx.x * blockDim.x + threadIdx.x;
    int v = i * 2;
    float c0 = __ldg(&b2[0]);
    float c1 = __ldg(&b2[1]);
    gdep_sync();                           // wait for k_scatter2
    if (v + 1 < n) {
        float2 dv2 = *reinterpret_cast<const float2*>(g_dinv + v);
        float4 ac  = *reinterpret_cast<const float4*>(g_acc + v);
        const __half2* gp = g_gd + v;
        float2 ga = __half22float2(gp[0]);
        float2 gb = __half22float2(gp[1]);
        float4 o;
        o.x = dv2.x * (ac.x + ga.x) + c0;
        o.y = dv2.x * (ac.y + ga.y) + c1;
        o.z = dv2.y * (ac.z + gb.x) + c0;
        o.w = dv2.y * (ac.w + gb.y) + c1;
        *reinterpret_cast<float4*>(out + v) = o;
    } else if (v < n) {                    // odd-N tail
        float dv = g_dinv[v];
        float2 acc = g_acc[v];
        float2 gd  = __half22float2(g_gd[v]);
        out[v] = make_float2(dv * (acc.x + gd.x) + c0,
                             dv * (acc.y + gd.y) + c1);
    }
}

// host-side helper: launch with PDL (programmatic stream serialization)
template <typename K, typename... Args>
static void launch_pdl(K kernel, dim3 grid, dim3 block, Args... args) {
    cudaLaunchConfig_t cfg = {};
    cfg.gridDim  = grid;
    cfg.blockDim = block;
    cfg.dynamicSmemBytes = 0;
    cfg.stream = 0;
    cudaLaunchAttribute attr[1];
    attr[0].id = cudaLaunchAttributeProgrammaticStreamSerialization;
    attr[0].val.programmaticStreamSerializationAllowed = 1;
    cfg.attrs = attr;
    cfg.numAttrs = 1;
    cudaLaunchKernelEx(&cfg, kernel, args...);
}

extern "C" void kernel_launch(void* const* d_in, const int* in_sizes, int n_in,
                              void* d_out, int out_size) {
    const float* x  = (const float*)d_in[0];
    const int*   ei = (const int*)d_in[1];       // [2, E]: row0=src, row1=dst
    const float* W1 = (const float*)d_in[2];
    const float* b1 = (const float*)d_in[3];
    const float* W2 = (const float*)d_in[4];
    const float* b2 = (const float*)d_in[5];
    float2* out = (float2*)d_out;

    int N = in_sizes[0];                 // C_IN = 1
    int E = in_sizes[1] / 2;
    const int* src = ei;
    const int* dst = ei + E;

    const int TE = 512;                  // edge kernels: fewer CTAs, same threads
    const int TN = 256;
    int nHalf   = (N + 1) / 2;
    int gridN2  = (nHalf + TN - 1) / TN; // 2 nodes/thread kernels
    int E4      = (E + 3) / 4;
    int gridE4  = (E4 + TE - 1) / TE;

    // zero deg via DMA before the kernel chain
    void* degPtr = nullptr;
    cudaGetSymbolAddress(&degPtr, g_deg);
    cudaMemsetAsync(degPtr, 0, N * sizeof(float));

    launch_pdl(k_deg,      dim3(gridE4), dim3(TE), dst, E);
    launch_pdl(k_dinv_px,  dim3(gridN2), dim3(TN), x, N);
    launch_pdl(k_scatter1, dim3(gridE4), dim3(TE), src, dst, E);
    launch_pdl(k_node,     dim3(gridN2), dim3(TN), W1, b1, W2, N);
    launch_pdl(k_scatter2, dim3(gridE4), dim3(TE), src, dst, E);
    launch_pdl(k_final,    dim3(gridN2), dim3(TN), b2, out, N);
}

// round 14
// speedup vs baseline: 1.0210x; 1.0210x over previous
#include <cuda_runtime.h>
#include <cuda_fp16.h>

#define MAX_N 100000
#define HID   16

// Scratch (allocation-free rule: __device__ globals)
__device__ __align__(16) float   g_deg[MAX_N];
__device__ __align__(16) float   g_dinv[MAX_N];
__device__ __align__(16) __half  g_px[MAX_N];   // fp16: dinv[v]*x[v]
__device__ __align__(16) float   g_s[MAX_N];    // layer-1 aggregate accumulator
__device__ __align__(16) __half2 g_gd[MAX_N];   // fp16x2: dinv[v]*g[v,0:2]
__device__ __align__(16) float2  g_acc[MAX_N];  // layer-2 aggregate accumulator

// no-return global reductions (REDG)
__device__ __forceinline__ void red_add_f32(float* addr, float v) {
    asm volatile("red.global.relaxed.gpu.add.f32 [%0], %1;"
                 :: "l"(addr), "f"(v) : "memory");
}
__device__ __forceinline__ void red_add_v2(float2* addr, float a, float b) {
    asm volatile("red.global.relaxed.gpu.add.v2.f32 [%0], {%1, %2};"
                 :: "l"(addr), "f"(a), "f"(b) : "memory");
}

__device__ __forceinline__ int4 ldcs_int4(const int* p) {
    return __ldcs(reinterpret_cast<const int4*>(p));
}

__device__ __forceinline__ void gdep_sync() {
#if __CUDA_ARCH__ >= 900
    cudaGridDependencySynchronize();
#endif
}
__device__ __forceinline__ void pdl_trigger() {
#if __CUDA_ARCH__ >= 900
    cudaTriggerProgrammaticLaunchCompletion();
#endif
}

// degree histogram over dst, 4 edges/thread
__global__ void k_deg(const int* __restrict__ dst, int E) {
    int i = blockIdx.x * blockDim.x + threadIdx.x;
    int base = i * 4;
    if (base + 3 < E) {
        int4 d = ldcs_int4(dst + base);
        gdep_sync();                       // wait for g_deg memset
        red_add_f32(&g_deg[d.x], 1.0f);
        red_add_f32(&g_deg[d.y], 1.0f);
        red_add_f32(&g_deg[d.z], 1.0f);
        red_add_f32(&g_deg[d.w], 1.0f);
        pdl_trigger();
    } else {
        gdep_sync();
        for (int j = base; j < E; ++j)
            red_add_f32(&g_deg[dst[j]], 1.0f);
        pdl_trigger();
    }
}

// 2 nodes/thread, vectorized (N even)
__global__ void k_dinv_px(const float* __restrict__ x, int n) {
    int i = blockIdx.x * blockDim.x + threadIdx.x;
    int v = i * 2;
    if (v + 1 < n) {
        float2 xv = *reinterpret_cast<const float2*>(x + v);
        gdep_sync();                       // wait for k_deg
        float2 dg = *reinterpret_cast<const float2*>(g_deg + v);
        float d0 = rsqrtf(dg.x + 1.0f);    // +1 = self-loop
        float d1 = rsqrtf(dg.y + 1.0f);
        *reinterpret_cast<float2*>(g_dinv + v) = make_float2(d0, d1);
        *reinterpret_cast<__half2*>(g_px + v)  = __floats2half2_rn(d0 * xv.x, d1 * xv.y);
        *reinterpret_cast<float2*>(g_s + v)    = make_float2(0.0f, 0.0f);
        pdl_trigger();
    } else {
        gdep_sync();
        for (int j = v; j < n; ++j) {
            float dv = rsqrtf(g_deg[j] + 1.0f);
            g_dinv[j] = dv;
            g_px[j]   = __float2half_rn(dv * x[j]);
            g_s[j]    = 0.0f;
        }
        pdl_trigger();
    }
}

// scatter 1: s[dst] += px[src], 4 edges/thread
__global__ void k_scatter1(const int* __restrict__ src,
                           const int* __restrict__ dst, int E) {
    int i = blockIdx.x * blockDim.x + threadIdx.x;
    int base = i * 4;
    if (base + 3 < E) {
        int4 s4 = ldcs_int4(src + base);
        int4 d4 = ldcs_int4(dst + base);
        gdep_sync();                       // wait for k_dinv_px (px, s=0)
        float p0 = __half2float(__ldg(&g_px[s4.x]));
        float p1 = __half2float(__ldg(&g_px[s4.y]));
        float p2 = __half2float(__ldg(&g_px[s4.z]));
        float p3 = __half2float(__ldg(&g_px[s4.w]));
        red_add_f32(&g_s[d4.x], p0);
        red_add_f32(&g_s[d4.y], p1);
        red_add_f32(&g_s[d4.z], p2);
        red_add_f32(&g_s[d4.w], p3);
        pdl_trigger();
    } else {
        gdep_sync();
        for (int j = base; j < E; ++j)
            red_add_f32(&g_s[dst[j]], __half2float(__ldg(&g_px[src[j]])));
        pdl_trigger();
    }
}

// per-node dense, 2 nodes/thread: finalize s, W1/b1 + relu, W2, pre-scale by dinv
// prologue: weights staged to SMEM (inputs — safe pre-dependency)
__global__ void k_node(const float* __restrict__ W1, const float* __restrict__ b1,
                       const float* __restrict__ W2, int n) {
    __shared__ float sw1[HID], sb1[HID], sw2[2 * HID];
    int t = threadIdx.x;
    if (t < HID)     { sw1[t] = __ldg(&W1[t]); sb1[t] = __ldg(&b1[t]); }
    if (t < 2 * HID) { sw2[t] = __ldg(&W2[t]); }
    __syncthreads();
    gdep_sync();                           // wait for k_scatter1
    int v = (blockIdx.x * blockDim.x + t) * 2;
    if (v + 1 < n) {
        float2 dv2 = *reinterpret_cast<const float2*>(g_dinv + v);
        float2 s2  = *reinterpret_cast<const float2*>(g_s + v);
        float2 px2 = __half22float2(*reinterpret_cast<const __half2*>(g_px + v));
        float sa = dv2.x * (s2.x + px2.x);   // + self-loop terms
        float sb = dv2.y * (s2.y + px2.y);
        float a0 = 0.0f, a1 = 0.0f, c0 = 0.0f, c1 = 0.0f;
#pragma unroll
        for (int j = 0; j < HID; ++j) {
            float ha = fmaxf(fmaf(sa, sw1[j], sb1[j]), 0.0f);
            float hb = fmaxf(fmaf(sb, sw1[j], sb1[j]), 0.0f);
            a0 = fmaf(ha, sw2[2 * j + 0], a0);
            a1 = fmaf(ha, sw2[2 * j + 1], a1);
            c0 = fmaf(hb, sw2[2 * j + 0], c0);
            c1 = fmaf(hb, sw2[2 * j + 1], c1);
        }
        __half2* gp = g_gd + v;
        gp[0] = __floats2half2_rn(dv2.x * a0, dv2.x * a1);
        gp[1] = __floats2half2_rn(dv2.y * c0, dv2.y * c1);
        *reinterpret_cast<float4*>(g_acc + v) = make_float4(0.f, 0.f, 0.f, 0.f);
    } else if (v < n) {                    // odd-N tail (not hit for N=100000)
        float dv = g_dinv[v];
        float sv = dv * (g_s[v] + __half2float(g_px[v]));
        float a0 = 0.0f, a1 = 0.0f;
#pragma unroll
        for (int j = 0; j < HID; ++j) {
            float h = fmaxf(fmaf(sv, sw1[j], sb1[j]), 0.0f);
            a0 = fmaf(h, sw2[2 * j + 0], a0);
            a1 = fmaf(h, sw2[2 * j + 1], a1);
        }
        g_gd[v]  = __floats2half2_rn(dv * a0, dv * a1);
        g_acc[v] = make_float2(0.0f, 0.0f);
    }
    pdl_trigger();
}

// scatter 2: acc[dst] += gd[src] via ONE red.v2 per edge, 4 edges/thread
__global__ void k_scatter2(const int* __restrict__ src,
                           const int* __restrict__ dst, int E) {
    int i = blockIdx.x * blockDim.x + threadIdx.x;
    int base = i * 4;
    if (base + 3 < E) {
        int4 s4 = ldcs_int4(src + base);
        int4 d4 = ldcs_int4(dst + base);
        gdep_sync();                       // wait for k_node (gd, acc=0)
        float2 a0 = __half22float2(__ldg(&g_gd[s4.x]));
        float2 a1 = __half22float2(__ldg(&g_gd[s4.y]));
        float2 a2 = __half22float2(__ldg(&g_gd[s4.z]));
        float2 a3 = __half22float2(__ldg(&g_gd[s4.w]));
        red_add_v2(&g_acc[d4.x], a0.x, a0.y);
        red_add_v2(&g_acc[d4.y], a1.x, a1.y);
        red_add_v2(&g_acc[d4.z], a2.x, a2.y);
        red_add_v2(&g_acc[d4.w], a3.x, a3.y);
        pdl_trigger();
    } else {
        gdep_sync();
        for (int j = base; j < E; ++j) {
            float2 a = __half22float2(__ldg(&g_gd[src[j]]));
            red_add_v2(&g_acc[dst[j]], a.x, a.y);
        }
        pdl_trigger();
    }
}

// 2 nodes/thread; prologue: bias loads (inputs); float4 store
__global__ void k_final(const float* __restrict__ b2, float2* __restrict__ out, int n) {
    int i = blockIdx.x * blockDim.x + threadIdx.x;
    int v = i * 2;
    float c0 = __ldg(&b2[0]);
    float c1 = __ldg(&b2[1]);
    gdep_sync();                           // wait for k_scatter2
    if (v + 1 < n) {
        float2 dv2 = *reinterpret_cast<const float2*>(g_dinv + v);
        float4 ac  = *reinterpret_cast<const float4*>(g_acc + v);
        const __half2* gp = g_gd + v;
        float2 ga = __half22float2(gp[0]);
        float2 gb = __half22float2(gp[1]);
        float4 o;
        o.x = dv2.x * (ac.x + ga.x) + c0;
        o.y = dv2.x * (ac.y + ga.y) + c1;
        o.z = dv2.y * (ac.z + gb.x) + c0;
        o.w = dv2.y * (ac.w + gb.y) + c1;
        *reinterpret_cast<float4*>(out + v) = o;
    } else if (v < n) {                    // odd-N tail
        float dv = g_dinv[v];
        float2 acc = g_acc[v];
        float2 gd  = __half22float2(g_gd[v]);
        out[v] = make_float2(dv * (acc.x + gd.x) + c0,
                             dv * (acc.y + gd.y) + c1);
    }
}

// host-side helper: launch with PDL (programmatic stream serialization)
template <typename K, typename... Args>
static void launch_pdl(K kernel, dim3 grid, dim3 block, Args... args) {
    cudaLaunchConfig_t cfg = {};
    cfg.gridDim  = grid;
    cfg.blockDim = block;
    cfg.dynamicSmemBytes = 0;
    cfg.stream = 0;
    cudaLaunchAttribute attr[1];
    attr[0].id = cudaLaunchAttributeProgrammaticStreamSerialization;
    attr[0].val.programmaticStreamSerializationAllowed = 1;
    cfg.attrs = attr;
    cfg.numAttrs = 1;
    cudaLaunchKernelEx(&cfg, kernel, args...);
}

extern "C" void kernel_launch(void* const* d_in, const int* in_sizes, int n_in,
                              void* d_out, int out_size) {
    const float* x  = (const float*)d_in[0];
    const int*   ei = (const int*)d_in[1];       // [2, E]: row0=src, row1=dst
    const float* W1 = (const float*)d_in[2];
    const float* b1 = (const float*)d_in[3];
    const float* W2 = (const float*)d_in[4];
    const float* b2 = (const float*)d_in[5];
    float2* out = (float2*)d_out;

    int N = in_sizes[0];                 // C_IN = 1
    int E = in_sizes[1] / 2;
    const int* src = ei;
    const int* dst = ei + E;

    const int T = 256;                   // best-measured config everywhere
    int nHalf   = (N + 1) / 2;
    int gridN2  = (nHalf + T - 1) / T;   // 2 nodes/thread kernels
    int E4      = (E + 3) / 4;
    int gridE4  = (E4 + T - 1) / T;

    // zero deg via DMA before the kernel chain (stateless, proven)
    void* degPtr = nullptr;
    cudaGetSymbolAddress(&degPtr, g_deg);
    cudaMemsetAsync(degPtr, 0, N * sizeof(float));

    launch_pdl(k_deg,      dim3(gridE4), dim3(T), dst, E);
    launch_pdl(k_dinv_px,  dim3(gridN2), dim3(T), x, N);
    launch_pdl(k_scatter1, dim3(gridE4), dim3(T), src, dst, E);
    launch_pdl(k_node,     dim3(gridN2), dim3(T), W1, b1, W2, N);
    launch_pdl(k_scatter2, dim3(gridE4), dim3(T), src, dst, E);
    launch_pdl(k_final,    dim3(gridN2), dim3(T), b2, out, N);
}